// round 6
// baseline (speedup 1.0000x reference)
#include <cuda_runtime.h>
#include <cuda_bf16.h>
#include <math.h>
#include <stdint.h>

// LSTM scan: B=256, T=512, D=1, H=512. W:[513,2048] (i,j,f,o). out fp32 [B,T,H].
// bf16 HMMA (mma.sync.m16n8k16), fp32 via 3-term split: ahi*whi + ahi*wlo + alo*whi.
// Round 6: 8 warps/CTA (K-split warp pairs), early prefetch, dual z accumulators.

#define BATCH 256
#define TSTEPS 512
#define HDIM 512
#define GDIM 2048
#define KEFF 1536
#define KC 32
#define NCH 48
#define NBUF 4
#define APITCH 80        // 64B row + 16 pad
#define TILEB 5120       // 64 rows * APITCH
#define BUFB  10240
#define ZPITCH 66

__device__ __align__(16) __nv_bfloat16 g_Wp[GDIM * KEFF];
__device__ __align__(16) __nv_bfloat16 g_A[2][BATCH * 1024];
__device__ float g_c[BATCH * HDIM];

__device__ __forceinline__ uint32_t cvta_s(const void* p) {
    return (uint32_t)__cvta_generic_to_shared(p);
}
__device__ __forceinline__ void cp16(uint32_t dst, const void* src) {
    asm volatile("cp.async.cg.shared.global [%0], [%1], 16;" :: "r"(dst), "l"(src));
}
#define CP_COMMIT() asm volatile("cp.async.commit_group;")
#define CP_WAIT3()  asm volatile("cp.async.wait_group 3;")

#define LDSM_X4(r0, r1, r2, r3, a)                                             \
    asm volatile("ldmatrix.sync.aligned.m8n8.x4.shared.b16 {%0,%1,%2,%3}, [%4];" \
                 : "=r"(r0), "=r"(r1), "=r"(r2), "=r"(r3) : "r"(a))

#define MMA16816(c, a0, a1, a2, a3, b0, b1)                                    \
    asm volatile("mma.sync.aligned.m16n8k16.row.col.f32.bf16.bf16.f32 "        \
                 "{%0,%1,%2,%3}, {%4,%5,%6,%7}, {%8,%9}, {%0,%1,%2,%3};"       \
                 : "+f"((c)[0]), "+f"((c)[1]), "+f"((c)[2]), "+f"((c)[3])      \
                 : "r"(a0), "r"(a1), "r"(a2), "r"(a3), "r"(b0), "r"(b1))

__device__ __forceinline__ float sigmoidf_(float v) {
    return 1.0f / (1.0f + expf(-v));
}

// W'[p][k]: p = h*4+g -> gcol = g*512+h; k: [0,512)=Whi, [512,1024)=Wlo, [1024,1536)=Whi
__global__ void conv_w(const float* __restrict__ W) {
    int idx = blockIdx.x * blockDim.x + threadIdx.x;
    if (idx >= GDIM * KEFF) return;
    int p = idx / KEFF;
    int k = idx - p * KEFF;
    int g = p & 3, h = p >> 2;
    int seg = k >> 9, kk = k & 511;
    float w = W[(size_t)(kk + 1) * GDIM + g * HDIM + h];
    __nv_bfloat16 hi = __float2bfloat16(w);
    g_Wp[idx] = (seg == 1) ? __float2bfloat16(w - __bfloat162float(hi)) : hi;
}

__global__ void lstm_init() {
    int i = blockIdx.x * blockDim.x + threadIdx.x;
    if (i < BATCH * HDIM) g_c[i] = 0.0f;
    if (i < BATCH * 1024) {
        g_A[0][i] = __float2bfloat16(0.0f);
        g_A[1][i] = __float2bfloat16(0.0f);
    }
}

// grid (32 nb, 4 mb) = 128 CTAs, 256 threads (8 warps).
// warp: ks = wid>>2 (k-half of each chunk), 2x2 tile grid of 32x32 warp tiles.
__global__ void __launch_bounds__(256, 1) lstm_step(
    const float* __restrict__ x,
    const float* __restrict__ W,
    const float* __restrict__ bias,
    float* __restrict__ out,
    int t)
{
    __shared__ __align__(128) char smem_raw[NBUF * BUFB];   // 40 KB; z aliases
    __shared__ float s_w0[64], s_b[64];

    const __nv_bfloat16* __restrict__ Ain = g_A[t & 1];
    __nv_bfloat16* __restrict__ Aout = g_A[(t + 1) & 1];

    const int tid = threadIdx.x;
    const int wid = tid >> 5;
    const int lane = tid & 31;
    const int nb = blockIdx.x;
    const int m_base = blockIdx.y * 64;

    const uint32_t sbase = cvta_s(smem_raw);
    const int ks = wid >> 2;               // k-half 0/1
    const int w2 = wid & 3;
    const int warp_m = (w2 >> 1) * 32;
    const int warp_n = (w2 & 1) * 32;

    if (tid < 64) {
        int gcol = (tid & 3) * HDIM + nb * 16 + (tid >> 2);
        s_w0[tid] = W[gcol];
        s_b[tid] = bias[gcol];
    }

    // loaders: A row 64B = 4x16B; 256 threads -> 1 A + 1 B cp16 each
    const int lrow = tid >> 2, lc = tid & 3;

    auto prefetch = [&](int c) {
        int buf = c & 3;
        int seg = c >> 4;
        int a_off = ((seg == 2) ? 512 : 0) + (c & 15) * KC;
        int w_off = c * KC;
        uint32_t ab = sbase + buf * BUFB;
        cp16(ab + lrow * APITCH + lc * 16,
             &Ain[(size_t)(m_base + lrow) * 1024 + a_off + lc * 8]);
        cp16(ab + TILEB + lrow * APITCH + lc * 16,
             &g_Wp[(size_t)(nb * 64 + lrow) * KEFF + w_off + lc * 8]);
    };

    float acc[2][4][4] = {};

    prefetch(0); CP_COMMIT();
    prefetch(1); CP_COMMIT();
    prefetch(2); CP_COMMIT();

    const uint32_t a_row = warp_m + (lane & 15);
    const uint32_t a_colb = (lane >> 4) * 16;
    const uint32_t b_row = warp_n + (lane & 7) + ((lane >> 4) << 3);
    const uint32_t b_colb = ((lane >> 3) & 1) * 16;

    #pragma unroll 1
    for (int c = 0; c < NCH; c++) {
        // early prefetch: target buffer was drained before previous trailing sync
        if (c + 3 < NCH) prefetch(c + 3);
        CP_COMMIT();
        CP_WAIT3();
        __syncthreads();

        const uint32_t ab = sbase + (c & 3) * BUFB;
        const uint32_t bb = ab + TILEB;

        uint32_t a0, a1, a2, a3, a4, a5, a6, a7;
        uint32_t b00, b01, b10, b11, b20, b21, b30, b31;
        uint32_t aaddr = ab + a_row * APITCH + ks * 32 + a_colb;
        LDSM_X4(a0, a1, a2, a3, aaddr);
        LDSM_X4(a4, a5, a6, a7, aaddr + 16 * APITCH);
        uint32_t baddr = bb + b_row * APITCH + ks * 32 + b_colb;
        LDSM_X4(b00, b01, b10, b11, baddr);
        LDSM_X4(b20, b21, b30, b31, baddr + 16 * APITCH);

        MMA16816(acc[0][0], a0, a1, a2, a3, b00, b01);
        MMA16816(acc[0][1], a0, a1, a2, a3, b10, b11);
        MMA16816(acc[0][2], a0, a1, a2, a3, b20, b21);
        MMA16816(acc[0][3], a0, a1, a2, a3, b30, b31);
        MMA16816(acc[1][0], a4, a5, a6, a7, b00, b01);
        MMA16816(acc[1][1], a4, a5, a6, a7, b10, b11);
        MMA16816(acc[1][2], a4, a5, a6, a7, b20, b21);
        MMA16816(acc[1][3], a4, a5, a6, a7, b30, b31);

        __syncthreads();
    }

    // ---- dual z accumulators (alias ring buffers): z0 for ks=0, z1 for ks=1
    float* z0 = (float*)smem_raw;                 // [64][ZPITCH]
    float* z1 = z0 + 64 * ZPITCH;                 // total 33.8 KB < 40 KB
    float* zw = ks ? z1 : z0;
    #pragma unroll
    for (int mf = 0; mf < 2; mf++)
        #pragma unroll
        for (int nf = 0; nf < 4; nf++) {
            int row = warp_m + mf * 16 + (lane >> 2);
            int col = warp_n + nf * 8 + (lane & 3) * 2;
            *(float2*)&zw[row * ZPITCH + col] =
                make_float2(acc[mf][nf][0], acc[mf][nf][1]);
            *(float2*)&zw[(row + 8) * ZPITCH + col] =
                make_float2(acc[mf][nf][2], acc[mf][nf][3]);
        }
    __syncthreads();

    // ---- gate fusion: 4 (batch,h) outputs per thread ----
    #pragma unroll
    for (int i = 0; i < 4; i++) {
        int o = i * 256 + tid;
        int r = o >> 4;
        int h = o & 15;
        int b_row = m_base + r;
        int h_col = nb * 16 + h;

        float xv = x[b_row * TSTEPS + t];   // D == 1
        const float* za = &z0[r * ZPITCH + h * 4];
        const float* zb = &z1[r * ZPITCH + h * 4];

        float zi = za[0] + zb[0] + fmaf(xv, s_w0[h * 4 + 0], s_b[h * 4 + 0]);
        float zj = za[1] + zb[1] + fmaf(xv, s_w0[h * 4 + 1], s_b[h * 4 + 1]);
        float zf = za[2] + zb[2] + fmaf(xv, s_w0[h * 4 + 2], s_b[h * 4 + 2]);
        float zo = za[3] + zb[3] + fmaf(xv, s_w0[h * 4 + 3], s_b[h * 4 + 3]);

        int sidx = b_row * HDIM + h_col;
        float c_old = g_c[sidx];
        float fg = sigmoidf_(zf + 1.0f);
        float ig = sigmoidf_(zi);
        float og = sigmoidf_(zo);
        float cn = c_old * fg + ig * tanhf(zj);
        float hn = tanhf(cn) * og;

        g_c[sidx] = cn;
        out[(size_t)b_row * (TSTEPS * HDIM) + (size_t)t * HDIM + h_col] = hn;
        __nv_bfloat16 hi = __float2bfloat16(hn);
        __nv_bfloat16 lo = __float2bfloat16(hn - __bfloat162float(hi));
        Aout[(size_t)b_row * 1024 + h_col] = hi;
        Aout[(size_t)b_row * 1024 + 512 + h_col] = lo;
    }
}

extern "C" void kernel_launch(void* const* d_in, const int* in_sizes, int n_in,
                              void* d_out, int out_size) {
    const float* x    = (const float*)d_in[0];
    const float* W    = (const float*)d_in[1];
    const float* bias = (const float*)d_in[2];
    float* out = (float*)d_out;
    (void)in_sizes; (void)n_in; (void)out_size;

    conv_w<<<(GDIM * KEFF + 255) / 256, 256>>>(W);
    lstm_init<<<(BATCH * 1024 + 255) / 256, 256>>>();

    dim3 grid(32, 4);
    for (int t = 0; t < TSTEPS; t++) {
        lstm_step<<<grid, 256>>>(x, W, bias, out, t);
    }
}